// round 1
// baseline (speedup 1.0000x reference)
#include <cuda_runtime.h>
#include <cstdint>

#define TPB     256
#define NB      128
#define SEQLEN  8194
#define NL      2048
#define DD      128
#define NT      128
#define NTILES  16
#define HP      132
#define WP      132

// shared memory layout (bytes)
#define OFF_WT    0        // 128*132 f32 = 67584
#define OFF_HS    67584    // 128*132 f32 = 67584
#define OFF_M     135168   // 3*32*26 f32 = 9984
#define OFF_SSEQ  145152   // 4*132 i32  = 2112
#define OFF_EBUF  147264   // 2048 f32   = 8192
#define OFF_RED   155456   // 128*17 f32 = 8704
#define OFF_BSH   164160   // 32 f32     = 128
#define OFF_SRED  164288   // 64 f32     = 256
#define SMEM_BYTES 164544

typedef unsigned long long ull;

__device__ __forceinline__ void fma2(ull& acc, ull a, ull b) {
    asm("fma.rn.f32x2 %0, %1, %2, %0;" : "+l"(acc) : "l"(a), "l"(b));
}
__device__ __forceinline__ ull pack2(float x) {
    ull r; unsigned u = __float_as_uint(x);
    asm("mov.b64 %0, {%1, %1};" : "=l"(r) : "r"(u));
    return r;
}
__device__ __forceinline__ void unpack2(ull v, float& lo, float& hi) {
    unsigned a, b;
    asm("mov.b64 {%0, %1}, %2;" : "=r"(a), "=r"(b) : "l"(v));
    lo = __uint_as_float(a); hi = __uint_as_float(b);
}
// accurate tanh: tanh(x) = sign(x) * (1 - 2/(e^{2|x|}+1)); __expf rel err ~1e-7
__device__ __forceinline__ float tanh_acc(float x) {
    float ax = fminf(fabsf(x), 15.0f);
    float t  = __expf(2.0f * ax);
    float r  = 1.0f - __fdividef(2.0f, t + 1.0f);
    return copysignf(r, x);
}

// Build one H tile: Hs[d][n] = relu(M0[c][t0]+M1[c][t1]+M2[c][t2]+b[c]),
// d = c*4+s, global position p = s*2048 + n0 + n. Internal syncs guard reuse.
__device__ __forceinline__ void build_tile(
    const int* __restrict__ seq, int b, int n0, int tid,
    const float* __restrict__ Msh, const float* __restrict__ bsh,
    int* sseq, float* Hs)
{
    for (int i = tid; i < 4 * 130; i += TPB) {
        int s = i / 130, o = i - s * 130;
        sseq[s * 132 + o] = seq[b * SEQLEN + s * NL + n0 + o];
    }
    __syncthreads();
    for (int i = tid; i < DD * NT; i += TPB) {
        int d = i >> 7, n = i & 127;
        int c = d >> 2, s = d & 3;
        int t0 = sseq[s * 132 + n];
        int t1 = sseq[s * 132 + n + 1];
        int t2 = sseq[s * 132 + n + 2];
        float v = Msh[c * 26 + t0] + Msh[(32 + c) * 26 + t1]
                + Msh[(64 + c) * 26 + t2] + bsh[c];
        Hs[d * HP + n] = fmaxf(v, 0.0f);
    }
    __syncthreads();
}

__global__ void __launch_bounds__(TPB, 1)
dingo_kernel(const int*   __restrict__ seq,
             const float* __restrict__ emb,
             const float* __restrict__ convw,
             const float* __restrict__ convb,
             const float* __restrict__ Wa,
             const float* __restrict__ va,
             float*       __restrict__ out)
{
    extern __shared__ char smem[];
    float* Wt   = (float*)(smem + OFF_WT);     // [128][132]  Wt[e][dw] = Wa[dw][e]
    float* Hs   = (float*)(smem + OFF_HS);     // [128][132]  Hs[d][n]
    float* Msh  = (float*)(smem + OFF_M);      // [3][32][26]
    int*   sseq = (int*)  (smem + OFF_SSEQ);   // [4][132]
    float* ebuf = (float*)(smem + OFF_EBUF);   // [2048]
    float* red  = (float*)(smem + OFF_RED);    // [128][17]
    float* bsh  = (float*)(smem + OFF_BSH);    // [32]
    float* sred = (float*)(smem + OFF_SRED);   // [64]

    const int b   = blockIdx.x;
    const int tid = threadIdx.x;
    const int tx  = tid & 15;      // n-direction (8 cols each)
    const int ty  = tid >> 4;      // dw-direction (8 rows each)

    // ---- setup: transpose W_a into shared, fold emb*conv into M table ----
    for (int i = tid; i < DD * DD; i += TPB) {
        int ei = i >> 7, dw = i & 127;                 // contiguous dw writes
        Wt[ei * WP + dw] = Wa[dw * DD + ei];
    }
    for (int i = tid; i < 3 * 32 * 26; i += TPB) {
        int k = i / 832, r = i - k * 832;
        int c = r / 26, t = r - c * 26;
        float acc = 0.0f;
        #pragma unroll
        for (int q = 0; q < 5; q++)
            acc += emb[t * 5 + q] * convw[(c * 5 + q) * 3 + k];
        Msh[(k * 32 + c) * 26 + t] = acc;
    }
    if (tid < 32) bsh[tid] = convb[tid];
    float var[8];
    #pragma unroll
    for (int i = 0; i < 8; i++) var[i] = va[ty * 8 + i];
    __syncthreads();

    // ---- pass 1: energies e[n] = v . tanh(Wa @ H[:,n]) per tile ----
    for (int tile = 0; tile < NTILES; tile++) {
        const int n0 = tile * NT;
        build_tile(seq, b, n0, tid, Msh, bsh, sseq, Hs);

        ull acc2[4][8];
        #pragma unroll
        for (int ii = 0; ii < 4; ii++)
            #pragma unroll
            for (int j = 0; j < 8; j++) acc2[ii][j] = 0ull;

        #pragma unroll 2
        for (int e = 0; e < DD; e++) {
            const ull* wr = reinterpret_cast<const ull*>(Wt + e * WP + ty * 8);
            ull a0 = wr[0], a1 = wr[1], a2 = wr[2], a3 = wr[3];
            const float4* hp = reinterpret_cast<const float4*>(Hs + e * HP + tx * 8);
            float4 h0 = hp[0], h1 = hp[1];
            ull hb0 = pack2(h0.x), hb1 = pack2(h0.y), hb2 = pack2(h0.z), hb3 = pack2(h0.w);
            ull hb4 = pack2(h1.x), hb5 = pack2(h1.y), hb6 = pack2(h1.z), hb7 = pack2(h1.w);
            #define GROW(ii, AR) \
                fma2(acc2[ii][0], AR, hb0); fma2(acc2[ii][1], AR, hb1); \
                fma2(acc2[ii][2], AR, hb2); fma2(acc2[ii][3], AR, hb3); \
                fma2(acc2[ii][4], AR, hb4); fma2(acc2[ii][5], AR, hb5); \
                fma2(acc2[ii][6], AR, hb6); fma2(acc2[ii][7], AR, hb7);
            GROW(0, a0) GROW(1, a1) GROW(2, a2) GROW(3, a3)
            #undef GROW
        }

        // tanh + v_a weighting, partial over this thread's 8 dw-pairs
        float p[8];
        #pragma unroll
        for (int j = 0; j < 8; j++) p[j] = 0.0f;
        #pragma unroll
        for (int ii = 0; ii < 4; ii++) {
            float vlo = var[2 * ii], vhi = var[2 * ii + 1];
            #pragma unroll
            for (int j = 0; j < 8; j++) {
                float lo, hi; unpack2(acc2[ii][j], lo, hi);
                p[j] += vlo * tanh_acc(lo) + vhi * tanh_acc(hi);
            }
        }
        #pragma unroll
        for (int j = 0; j < 8; j++) red[(tx * 8 + j) * 17 + ty] = p[j];
        __syncthreads();
        if (tid < 128) {
            float ee = 0.0f;
            #pragma unroll
            for (int t = 0; t < 16; t++) ee += red[tid * 17 + t];
            ebuf[n0 + tid] = ee;
        }
        // next build_tile's internal sync guards red/Hs reuse
    }
    __syncthreads();

    // ---- stable softmax over ebuf[0..2047], in place -> weights ----
    const int lane = tid & 31, wid = tid >> 5;
    float m = -3.4e38f;
    for (int i = tid; i < NL; i += TPB) m = fmaxf(m, ebuf[i]);
    #pragma unroll
    for (int off = 16; off; off >>= 1) m = fmaxf(m, __shfl_xor_sync(0xffffffffu, m, off));
    if (lane == 0) sred[wid] = m;
    __syncthreads();
    if (tid == 0) {
        float mm = sred[0];
        #pragma unroll
        for (int i = 1; i < 8; i++) mm = fmaxf(mm, sred[i]);
        sred[16] = mm;
    }
    __syncthreads();
    m = sred[16];
    float z = 0.0f;
    for (int i = tid; i < NL; i += TPB) z += __expf(ebuf[i] - m);
    #pragma unroll
    for (int off = 16; off; off >>= 1) z += __shfl_xor_sync(0xffffffffu, z, off);
    if (lane == 0) sred[24 + wid] = z;
    __syncthreads();
    if (tid == 0) {
        float zz = 0.0f;
        #pragma unroll
        for (int i = 0; i < 8; i++) zz += sred[24 + i];
        sred[17] = zz;
    }
    __syncthreads();
    const float invz = 1.0f / sred[17];
    for (int i = tid; i < NL; i += TPB) ebuf[i] = __expf(ebuf[i] - m) * invz;
    __syncthreads();

    // ---- pass 2: ctx[d] = sum_n w[n] * H[d][n] (rebuild H tiles, cheap) ----
    float ctxp[8];
    #pragma unroll
    for (int i = 0; i < 8; i++) ctxp[i] = 0.0f;
    for (int tile = 0; tile < NTILES; tile++) {
        const int n0 = tile * NT;
        build_tile(seq, b, n0, tid, Msh, bsh, sseq, Hs);
        float w8[8];
        #pragma unroll
        for (int j = 0; j < 8; j++) w8[j] = ebuf[n0 + tx * 8 + j];
        #pragma unroll
        for (int i = 0; i < 8; i++) {
            const float4* hr = reinterpret_cast<const float4*>(Hs + (ty * 8 + i) * HP + tx * 8);
            float4 x0 = hr[0], x1 = hr[1];
            ctxp[i] += x0.x * w8[0] + x0.y * w8[1] + x0.z * w8[2] + x0.w * w8[3]
                     + x1.x * w8[4] + x1.y * w8[5] + x1.z * w8[6] + x1.w * w8[7];
        }
        // next build_tile's internal sync guards Hs reuse
    }
    __syncthreads();
    #pragma unroll
    for (int i = 0; i < 8; i++) red[(ty * 8 + i) * 17 + tx] = ctxp[i];
    __syncthreads();
    if (tid < 128) {
        float cv = 0.0f;
        #pragma unroll
        for (int t = 0; t < 16; t++) cv += red[tid * 17 + t];
        out[b * DD + tid] = cv;
    }
}

extern "C" void kernel_launch(void* const* d_in, const int* in_sizes, int n_in,
                              void* d_out, int out_size)
{
    const int*   seq   = (const int*)  d_in[0];  // [128, 8194] int32
    const float* emb   = (const float*)d_in[1];  // [26, 5]
    const float* convw = (const float*)d_in[2];  // [32, 5, 3]
    const float* convb = (const float*)d_in[3];  // [32]
    const float* Wa    = (const float*)d_in[4];  // [128, 128]
    const float* va    = (const float*)d_in[5];  // [128]
    float*       out   = (float*)d_out;          // [128, 128]

    cudaFuncSetAttribute(dingo_kernel,
                         cudaFuncAttributeMaxDynamicSharedMemorySize, SMEM_BYTES);
    dingo_kernel<<<NB, TPB, SMEM_BYTES>>>(seq, emb, convw, convb, Wa, va, out);
}

// round 2
// speedup vs baseline: 1.2692x; 1.2692x over previous
#include <cuda_runtime.h>
#include <cstdint>

#define TPB     512
#define HTPB    256
#define NB      128
#define SEQLEN  8194
#define NL      2048
#define DD      128
#define NT      128
#define NTILES  16

// shared memory layout (bytes)
#define OFF_WT    0         // 128*128 f32 = 65536
#define OFF_HS    65536     // 2 * 128*128 f32 = 131072
#define OFF_M     196608    // 3*32*26 f32 = 9984
#define OFF_SSEQ  206592    // 2 * 4*132 i32 = 4224
#define OFF_EBUF  210816    // 2048 f32 = 8192
#define OFF_BSH   219008    // 32 f32 = 128
#define OFF_SRED  219136    // 64 f32 = 256
#define OFF_CTX   219392    // 512 f32 = 2048
#define SMEM_BYTES 221440

typedef unsigned long long ull;

__device__ __forceinline__ void fma2(ull& acc, ull a, ull b) {
    asm("fma.rn.f32x2 %0, %1, %2, %0;" : "+l"(acc) : "l"(a), "l"(b));
}
__device__ __forceinline__ ull pack2(float x) {
    ull r; unsigned u = __float_as_uint(x);
    asm("mov.b64 %0, {%1, %1};" : "=l"(r) : "r"(u));
    return r;
}
__device__ __forceinline__ void unpack2(ull v, float& lo, float& hi) {
    unsigned a, b;
    asm("mov.b64 {%0, %1}, %2;" : "=r"(a), "=r"(b) : "l"(v));
    lo = __uint_as_float(a); hi = __uint_as_float(b);
}
// accurate tanh: tanh(x) = sign(x) * (1 - 2/(e^{2|x|}+1)); __expf rel err ~1e-7
__device__ __forceinline__ float tanh_acc(float x) {
    float ax = fminf(fabsf(x), 15.0f);
    float t  = __expf(2.0f * ax);
    float r  = 1.0f - __fdividef(2.0f, t + 1.0f);
    return copysignf(r, x);
}
__device__ __forceinline__ void barU(int half) {
    asm volatile("bar.sync %0, %1;" :: "r"(1 + half), "r"(HTPB) : "memory");
}

__global__ void __launch_bounds__(TPB, 1)
dingo_kernel(const int*   __restrict__ seq,
             const float* __restrict__ emb,
             const float* __restrict__ convw,
             const float* __restrict__ convb,
             const float* __restrict__ Wa,
             const float* __restrict__ va,
             float*       __restrict__ out)
{
    extern __shared__ char smem[];
    float* Wt   = (float*)(smem + OFF_WT);     // [128][128]  Wt[e][dw] = Wa[dw][e]
    float* HsA  = (float*)(smem + OFF_HS);     // 2 x [128][128]
    float* Msh  = (float*)(smem + OFF_M);      // [3][32][26]
    int*   sqA  = (int*)  (smem + OFF_SSEQ);   // 2 x [4][132]
    float* ebuf = (float*)(smem + OFF_EBUF);   // [2048]
    float* bsh  = (float*)(smem + OFF_BSH);    // [32]
    float* sred = (float*)(smem + OFF_SRED);   // [64]
    float* ctxb = (float*)(smem + OFF_CTX);    // [512]

    const int b    = blockIdx.x;
    const int tid  = threadIdx.x;
    const int half = tid >> 8;
    const int t    = tid & 255;
    const int tx   = t & 15;       // n-direction (8 cols each)
    const int ty   = t >> 4;       // dw-direction (8 rows = 4 pairs)

    float* Hs   = HsA + half * (DD * NT);
    int*   sseq = sqA + half * (4 * 132);
    const int* seqb = seq + b * SEQLEN;

    // ---- setup (whole block): transpose W_a, fold emb*conv into M ----
    for (int i = tid; i < DD * DD; i += TPB) {
        int ei = i >> 7, dw = i & 127;
        Wt[ei * DD + dw] = Wa[dw * DD + ei];
    }
    for (int i = tid; i < 3 * 32 * 26; i += TPB) {
        int k = i / 832, r = i - k * 832;
        int c = r / 26, tt = r - c * 26;
        float acc = 0.0f;
        #pragma unroll
        for (int q = 0; q < 5; q++)
            acc += emb[tt * 5 + q] * convw[(c * 5 + q) * 3 + k];
        Msh[(k * 32 + c) * 26 + tt] = acc;
    }
    if (tid < 32) bsh[tid] = convb[tid];
    float var[8];
    #pragma unroll
    for (int i = 0; i < 8; i++) var[i] = va[ty * 8 + i];
    __syncthreads();

    // ---- pass 1: energies per half (tiles half*8 .. half*8+7) ----
    for (int tile8 = 0; tile8 < 8; tile8++) {
        const int tile = half * 8 + tile8;
        const int n0 = tile * NT;

        // stage sequence window
        for (int i = t; i < 4 * 130; i += HTPB) {
            int s = i / 130, o = i - s * 130;
            sseq[s * 132 + o] = seqb[s * NL + n0 + o];
        }
        barU(half);

        // build H tile: thread owns column n = t&127, rows d = (t>>7) + 2k
        {
            const int n  = t & 127;
            const int db = t >> 7;
            const int sA = db & 3;            // db in {0,1}
            const int sB = (db + 2) & 3;
            const int a0 = sseq[sA * 132 + n], a1 = sseq[sA * 132 + n + 1], a2 = sseq[sA * 132 + n + 2];
            const int b0 = sseq[sB * 132 + n], b1 = sseq[sB * 132 + n + 1], b2 = sseq[sB * 132 + n + 2];
            #pragma unroll 4
            for (int k = 0; k < 64; k++) {
                int d = db + 2 * k;
                int c = d >> 2;
                int u0, u1, u2;
                if ((k & 1) == 0) { u0 = a0; u1 = a1; u2 = a2; }
                else              { u0 = b0; u1 = b1; u2 = b2; }
                float v = Msh[c * 26 + u0] + Msh[(32 + c) * 26 + u1]
                        + Msh[(64 + c) * 26 + u2] + bsh[c];
                Hs[d * NT + n] = fmaxf(v, 0.0f);
            }
        }
        barU(half);

        // register-tiled GEMM: acc[dw-pair ii][n j]
        ull acc2[4][8];
        #pragma unroll
        for (int ii = 0; ii < 4; ii++)
            #pragma unroll
            for (int j = 0; j < 8; j++) acc2[ii][j] = 0ull;

        const float* wp = Wt + ty * 8;
        const float* hh = Hs + tx * 8;
        #pragma unroll 1
        for (int e = 0; e < DD; e++) {
            ulonglong2 wA = *(const ulonglong2*)(wp);
            ulonglong2 wB = *(const ulonglong2*)(wp + 4);
            float4 h0 = *(const float4*)(hh);
            float4 h1 = *(const float4*)(hh + 4);
            wp += DD; hh += NT;
            ull hb0 = pack2(h0.x), hb1 = pack2(h0.y), hb2 = pack2(h0.z), hb3 = pack2(h0.w);
            ull hb4 = pack2(h1.x), hb5 = pack2(h1.y), hb6 = pack2(h1.z), hb7 = pack2(h1.w);
            #define GROW(ii, AR) \
                fma2(acc2[ii][0], AR, hb0); fma2(acc2[ii][1], AR, hb1); \
                fma2(acc2[ii][2], AR, hb2); fma2(acc2[ii][3], AR, hb3); \
                fma2(acc2[ii][4], AR, hb4); fma2(acc2[ii][5], AR, hb5); \
                fma2(acc2[ii][6], AR, hb6); fma2(acc2[ii][7], AR, hb7);
            GROW(0, wA.x) GROW(1, wA.y) GROW(2, wB.x) GROW(3, wB.y)
            #undef GROW
        }

        // tanh + v_a weighting
        float p[8];
        #pragma unroll
        for (int j = 0; j < 8; j++) p[j] = 0.0f;
        #pragma unroll
        for (int ii = 0; ii < 4; ii++) {
            float vlo = var[2 * ii], vhi = var[2 * ii + 1];
            #pragma unroll
            for (int j = 0; j < 8; j++) {
                float lo, hi; unpack2(acc2[ii][j], lo, hi);
                p[j] += vlo * tanh_acc(lo) + vhi * tanh_acc(hi);
            }
        }
        barU(half);                       // all GEMM reads of Hs done
        float* red = Hs;                  // alias reduction scratch into Hs
        #pragma unroll
        for (int j = 0; j < 8; j++) red[(tx * 8 + j) * 17 + ty] = p[j];
        barU(half);
        if (t < 128) {
            float ee = 0.0f;
            #pragma unroll
            for (int q = 0; q < 16; q++) ee += red[t * 17 + q];
            ebuf[n0 + t] = ee;
        }
        barU(half);                       // red reads done before next build
    }
    __syncthreads();

    // ---- stable softmax over ebuf[0..2047] (all 512 threads) ----
    const int lane = tid & 31, wid = tid >> 5;
    float m = -3.4e38f;
    for (int i = tid; i < NL; i += TPB) m = fmaxf(m, ebuf[i]);
    #pragma unroll
    for (int off = 16; off; off >>= 1) m = fmaxf(m, __shfl_xor_sync(0xffffffffu, m, off));
    if (lane == 0) sred[wid] = m;
    __syncthreads();
    if (tid == 0) {
        float mm = sred[0];
        #pragma unroll
        for (int i = 1; i < 16; i++) mm = fmaxf(mm, sred[i]);
        sred[16] = mm;
    }
    __syncthreads();
    m = sred[16];
    float z = 0.0f;
    for (int i = tid; i < NL; i += TPB) z += __expf(ebuf[i] - m);
    #pragma unroll
    for (int off = 16; off; off >>= 1) z += __shfl_xor_sync(0xffffffffu, z, off);
    if (lane == 0) sred[24 + wid] = z;
    __syncthreads();
    if (tid == 0) {
        float zz = 0.0f;
        #pragma unroll
        for (int i = 0; i < 16; i++) zz += sred[24 + i];
        sred[17] = zz;
    }
    __syncthreads();
    const float invz = 1.0f / sred[17];
    for (int i = tid; i < NL; i += TPB) ebuf[i] = __expf(ebuf[i] - m) * invz;
    __syncthreads();

    // ---- pass 2: ctx[d] += w[n]*H[d][n], H computed in registers ----
    float ctxv = 0.0f;
    {
        const int d  = t & 127;
        const int nh = t >> 7;            // n-half: 0 or 1 (64 each)
        const int c  = d >> 2;
        const int s  = d & 3;
        const float bc = bsh[c];
        const float* M0 = Msh + c * 26;
        const float* M1 = Msh + 832 + c * 26;
        const float* M2 = Msh + 1664 + c * 26;
        for (int tile8 = 0; tile8 < 8; tile8++) {
            const int tile = half * 8 + tile8;
            const int n0 = tile * NT;
            for (int i = t; i < 4 * 130; i += HTPB) {
                int ss = i / 130, o = i - ss * 130;
                sseq[ss * 132 + o] = seqb[ss * NL + n0 + o];
            }
            barU(half);
            const int* sq = sseq + s * 132 + nh * 64;
            const float* wn = ebuf + n0 + nh * 64;
            int t0 = sq[0], t1 = sq[1];
            #pragma unroll 4
            for (int n = 0; n < 64; n++) {
                int t2 = sq[n + 2];
                float v = M0[t0] + M1[t1] + M2[t2] + bc;
                ctxv += wn[n] * fmaxf(v, 0.0f);
                t0 = t1; t1 = t2;
            }
            barU(half);                   // sseq reads done before next overwrite
        }
    }
    ctxb[tid] = ctxv;
    __syncthreads();
    if (tid < 128)
        out[b * DD + tid] = ctxb[tid] + ctxb[tid + 128] + ctxb[tid + 256] + ctxb[tid + 384];
}

extern "C" void kernel_launch(void* const* d_in, const int* in_sizes, int n_in,
                              void* d_out, int out_size)
{
    const int*   seq   = (const int*)  d_in[0];  // [128, 8194] int32
    const float* emb   = (const float*)d_in[1];  // [26, 5]
    const float* convw = (const float*)d_in[2];  // [32, 5, 3]
    const float* convb = (const float*)d_in[3];  // [32]
    const float* Wa    = (const float*)d_in[4];  // [128, 128]
    const float* va    = (const float*)d_in[5];  // [128]
    float*       out   = (float*)d_out;          // [128, 128]

    cudaFuncSetAttribute(dingo_kernel,
                         cudaFuncAttributeMaxDynamicSharedMemorySize, SMEM_BYTES);
    dingo_kernel<<<NB, TPB, SMEM_BYTES>>>(seq, emb, convw, convb, Wa, va, out);
}

// round 4
// speedup vs baseline: 2.0891x; 1.6460x over previous
#include <cuda_runtime.h>
#include <cuda_bf16.h>
#include <cstdint>

#define TPB     512
#define NB      128
#define SEQLEN  8194
#define NL      2048
#define DD      128
#define NT      128
#define NTILES  16
#define WSTR    272      // bytes per row (136 bf16) for W and H tiles

// shared memory layout (bytes)
#define OFF_WHI   0        // 128*272 = 34816
#define OFF_WLO   34816
#define OFF_HHI   69632
#define OFF_HLO   104448
#define OFF_MSH   139264   // 3*32*26 f32 = 9984
#define OFF_SSEQ  149248   // 4*132 i32 = 2112
#define OFF_VASH  151360   // 128 f32
#define OFF_EPART 151872   // 8*132 f32 = 4224
#define OFF_ESH   156096   // 128 f32
#define OFF_WSH   156608   // 128 f32
#define OFF_CTXB  157120   // 512 f32 = 2048
#define OFF_BSH   159168   // 32 f32
#define OFF_SCAL  159296   // 32 f32
#define SMEM_BYTES 159424

__device__ __forceinline__ uint32_t smem_u32(const void* p) {
    uint32_t a;
    asm("{ .reg .u64 t; cvta.to.shared.u64 t, %1; cvt.u32.u64 %0, t; }" : "=r"(a) : "l"(p));
    return a;
}
__device__ __forceinline__ void ldsm_x4(uint32_t& r0, uint32_t& r1, uint32_t& r2, uint32_t& r3, uint32_t a) {
    asm volatile("ldmatrix.sync.aligned.m8n8.x4.shared.b16 {%0,%1,%2,%3}, [%4];"
                 : "=r"(r0), "=r"(r1), "=r"(r2), "=r"(r3) : "r"(a));
}
__device__ __forceinline__ void ldsm_x2(uint32_t& r0, uint32_t& r1, uint32_t a) {
    asm volatile("ldmatrix.sync.aligned.m8n8.x2.shared.b16 {%0,%1}, [%2];"
                 : "=r"(r0), "=r"(r1) : "r"(a));
}
__device__ __forceinline__ void mma16816(float* c, uint32_t a0, uint32_t a1, uint32_t a2, uint32_t a3,
                                         uint32_t b0, uint32_t b1) {
    asm volatile("mma.sync.aligned.m16n8k16.row.col.f32.bf16.bf16.f32 "
                 "{%0,%1,%2,%3}, {%4,%5,%6,%7}, {%8,%9}, {%0,%1,%2,%3};"
                 : "+f"(c[0]), "+f"(c[1]), "+f"(c[2]), "+f"(c[3])
                 : "r"(a0), "r"(a1), "r"(a2), "r"(a3), "r"(b0), "r"(b1));
}
// accurate tanh: sign(x)*(1 - 2/(e^{2|x|}+1)); __expf rel err ~1e-7
__device__ __forceinline__ float tanh_acc(float x) {
    float ax = fminf(fabsf(x), 15.0f);
    float t  = __expf(2.0f * ax);
    float r  = 1.0f - __fdividef(2.0f, t + 1.0f);
    return copysignf(r, x);
}

__global__ void __launch_bounds__(TPB, 1)
dingo_kernel(const int*   __restrict__ seq,
             const float* __restrict__ emb,
             const float* __restrict__ convw,
             const float* __restrict__ convb,
             const float* __restrict__ Wa,
             const float* __restrict__ va,
             float*       __restrict__ out)
{
    extern __shared__ char smem[];
    const uint32_t sb = smem_u32(smem);
    float* Msh   = (float*)(smem + OFF_MSH);
    int*   sseq  = (int*)  (smem + OFF_SSEQ);
    float* vash  = (float*)(smem + OFF_VASH);
    float* epart = (float*)(smem + OFF_EPART);
    float* esh   = (float*)(smem + OFF_ESH);
    float* wsh   = (float*)(smem + OFF_WSH);
    float* ctxb  = (float*)(smem + OFF_CTXB);
    float* bsh   = (float*)(smem + OFF_BSH);
    float* scal  = (float*)(smem + OFF_SCAL);

    const int b    = blockIdx.x;
    const int tid  = threadIdx.x;
    const int wid  = tid >> 5;
    const int lane = tid & 31;
    const int* seqb = seq + b * SEQLEN;

    // ---- setup: W hi/lo bf16 split, row-major [dw][e] stride 272B ----
    for (int i = tid; i < DD * DD; i += TPB) {
        int dw = i >> 7, e = i & 127;
        float w = Wa[i];
        __nv_bfloat16 h = __float2bfloat16(w);
        float lo = w - __bfloat162float(h);
        __nv_bfloat16 l = __float2bfloat16(lo);
        *(__nv_bfloat16*)(smem + OFF_WHI + dw * WSTR + e * 2) = h;
        *(__nv_bfloat16*)(smem + OFF_WLO + dw * WSTR + e * 2) = l;
    }
    // fold emb*conv into M tables: M[k][c][t]
    for (int i = tid; i < 3 * 32 * 26; i += TPB) {
        int k = i / 832, r = i - k * 832;
        int c = r / 26, tt = r - c * 26;
        float acc = 0.0f;
        #pragma unroll
        for (int q = 0; q < 5; q++)
            acc += emb[tt * 5 + q] * convw[(c * 5 + q) * 3 + k];
        Msh[(k * 32 + c) * 26 + tt] = acc;
    }
    if (tid < 32)  bsh[tid] = convb[tid];
    if (tid < 128) vash[tid] = va[tid];
    if (tid == 0) { scal[0] = -3.4e38f; scal[1] = 0.0f; }
    __syncthreads();

    // warp roles for GEMM: 8 m-rows x 2 n-halves
    const int wm  = wid & 7;
    const int n0w = (wid >> 3) * 64;
    // ldmatrix per-thread addresses
    const uint32_t aRow = (uint32_t)(16 * wm + (lane & 7) + ((lane >> 3) & 1) * 8) * WSTR
                        + (uint32_t)((lane >> 4) & 1) * 16;
    const uint32_t aH0 = sb + OFF_WHI + aRow;
    const uint32_t aL0 = sb + OFF_WLO + aRow;
    const int ll = lane & 15;
    const uint32_t bRow = (uint32_t)(n0w + (ll & 7)) * WSTR + (uint32_t)((ll >> 3) & 1) * 16;
    const uint32_t bH0 = sb + OFF_HHI + bRow;
    const uint32_t bL0 = sb + OFF_HLO + bRow;

    float ctxAcc = 0.0f;

    for (int tile = 0; tile < NTILES; tile++) {
        const int n0 = tile * NT;

        // -- stage sequence windows --
        for (int i = tid; i < 4 * 130; i += TPB) {
            int s = i / 130, o = i - s * 130;
            sseq[s * 132 + o] = seqb[s * NL + n0 + o];
        }
        __syncthreads();

        // -- build H tile: Hn[n][e] bf16 hi/lo; thread: fixed n, e-pairs --
        {
            const int n  = tid & 127;
            const int p  = (tid >> 7) & 1;
            const int ch = tid >> 8;
            const int s0 = 2 * p, s1 = 2 * p + 1;
            const int a0 = sseq[s0*132+n], a1 = sseq[s0*132+n+1], a2 = sseq[s0*132+n+2];
            const int b0 = sseq[s1*132+n], b1 = sseq[s1*132+n+1], b2 = sseq[s1*132+n+2];
            const uint32_t rowb = (uint32_t)n * WSTR + (uint32_t)(64 * ch + 2 * p) * 2;
            #pragma unroll 4
            for (int ci = 0; ci < 16; ci++) {
                int c = ch * 16 + ci;
                float bb = bsh[c];
                float v0 = Msh[c*26+a0] + Msh[(32+c)*26+a1] + Msh[(64+c)*26+a2] + bb;
                float v1 = Msh[c*26+b0] + Msh[(32+c)*26+b1] + Msh[(64+c)*26+b2] + bb;
                v0 = fmaxf(v0, 0.0f); v1 = fmaxf(v1, 0.0f);
                uint32_t hip;   // lo half = v0 (e0), hi half = v1 (e0+1)
                asm("cvt.rn.bf16x2.f32 %0, %1, %2;" : "=r"(hip) : "f"(v1), "f"(v0));
                float h0 = __uint_as_float(hip << 16);
                float h1 = __uint_as_float(hip & 0xFFFF0000u);
                float l0 = v0 - h0, l1 = v1 - h1;
                uint32_t lop;
                asm("cvt.rn.bf16x2.f32 %0, %1, %2;" : "=r"(lop) : "f"(l1), "f"(l0));
                uint32_t off = rowb + (uint32_t)ci * 8u;
                *(uint32_t*)(smem + OFF_HHI + off) = hip;
                *(uint32_t*)(smem + OFF_HLO + off) = lop;
            }
        }
        __syncthreads();

        // -- GEMM: D[16wm..+16][n0w..+64] = (Whi+Wlo)(Hhi+Hlo), 4 bf16 terms --
        float acc[8][4];
        #pragma unroll
        for (int j = 0; j < 8; j++)
            #pragma unroll
            for (int q = 0; q < 4; q++) acc[j][q] = 0.0f;

        #pragma unroll 1
        for (int kk = 0; kk < 8; kk++) {
            const uint32_t ko = (uint32_t)kk * 32u;
            uint32_t ah0, ah1, ah2, ah3, al0, al1, al2, al3;
            ldsm_x4(ah0, ah1, ah2, ah3, aH0 + ko);
            ldsm_x4(al0, al1, al2, al3, aL0 + ko);
            #pragma unroll
            for (int j = 0; j < 8; j++) {
                const uint32_t bo = (uint32_t)j * (8u * WSTR) + ko;
                uint32_t bh0, bh1, bl0, bl1;
                ldsm_x2(bh0, bh1, bH0 + bo);
                ldsm_x2(bl0, bl1, bL0 + bo);
                mma16816(acc[j], ah0, ah1, ah2, ah3, bh0, bh1);
                mma16816(acc[j], ah0, ah1, ah2, ah3, bl0, bl1);
                mma16816(acc[j], al0, al1, al2, al3, bh0, bh1);
                mma16816(acc[j], al0, al1, al2, al3, bl0, bl1);
            }
        }

        // -- epilogue: tanh + va weighting, reduce over dw within warp --
        {
            const int g = lane >> 2, tc = lane & 3;
            const float va0 = vash[16 * wm + g];
            const float va1 = vash[16 * wm + 8 + g];
            #pragma unroll
            for (int j = 0; j < 8; j++) {
                float p0 = va0 * tanh_acc(acc[j][0]) + va1 * tanh_acc(acc[j][2]);
                float p1 = va0 * tanh_acc(acc[j][1]) + va1 * tanh_acc(acc[j][3]);
                #pragma unroll
                for (int off = 4; off <= 16; off <<= 1) {
                    p0 += __shfl_xor_sync(0xffffffffu, p0, off);
                    p1 += __shfl_xor_sync(0xffffffffu, p1, off);
                }
                if (lane < 4) {
                    epart[wm * 132 + n0w + j * 8 + 2 * tc]     = p0;
                    epart[wm * 132 + n0w + j * 8 + 2 * tc + 1] = p1;
                }
            }
        }
        __syncthreads();

        // -- e[n] combine + tile max --
        if (tid < 128) {
            float e = 0.0f;
            #pragma unroll
            for (int m = 0; m < 8; m++) e += epart[m * 132 + tid];
            esh[tid] = e;
            float mx = e;
            #pragma unroll
            for (int off = 16; off; off >>= 1)
                mx = fmaxf(mx, __shfl_xor_sync(0xffffffffu, mx, off));
            if (lane == 0) scal[8 + wid] = mx;
        }
        __syncthreads();
        if (tid == 0) {
            float mt = fmaxf(fmaxf(scal[8], scal[9]), fmaxf(scal[10], scal[11]));
            float m_new = fmaxf(scal[0], mt);
            scal[3] = __expf(scal[0] - m_new);   // alpha
            scal[2] = m_new;
            scal[0] = m_new;
        }
        __syncthreads();
        // -- tile weights + Z partials --
        if (tid < 128) {
            float wv = __expf(esh[tid] - scal[2]);
            wsh[tid] = wv;
            #pragma unroll
            for (int off = 16; off; off >>= 1)
                wv += __shfl_xor_sync(0xffffffffu, wv, off);
            if (lane == 0) scal[16 + wid] = wv;
        }
        __syncthreads();
        if (tid == 0)
            scal[1] = scal[1] * scal[3] + (scal[16] + scal[17] + scal[18] + scal[19]);
        // -- online ctx: thread (d, q) over its 32 n, H = hi + lo --
        {
            const float alpha = scal[3];
            const int d = tid & 127, q = tid >> 7;
            float ta = 0.0f;
            #pragma unroll 4
            for (int i = 0; i < 32; i++) {
                int nn = q * 32 + i;
                uint32_t o = (uint32_t)nn * WSTR + (uint32_t)d * 2u;
                uint32_t hi16 = *(const unsigned short*)(smem + OFF_HHI + o);
                uint32_t lo16 = *(const unsigned short*)(smem + OFF_HLO + o);
                float h = __uint_as_float(hi16 << 16) + __uint_as_float(lo16 << 16);
                ta += wsh[nn] * h;
            }
            ctxAcc = ctxAcc * alpha + ta;
        }
        __syncthreads();   // H/epart/esh/wsh reuse next tile
    }

    // ---- finalize: out[d] = sum_q ctx_q / Z ----
    ctxb[tid] = ctxAcc;
    __syncthreads();
    if (tid < 128) {
        float invz = 1.0f / scal[1];
        out[b * DD + tid] = (ctxb[tid] + ctxb[tid + 128] + ctxb[tid + 256] + ctxb[tid + 384]) * invz;
    }
}

extern "C" void kernel_launch(void* const* d_in, const int* in_sizes, int n_in,
                              void* d_out, int out_size)
{
    const int*   seq   = (const int*)  d_in[0];  // [128, 8194] int32
    const float* emb   = (const float*)d_in[1];  // [26, 5]
    const float* convw = (const float*)d_in[2];  // [32, 5, 3]
    const float* convb = (const float*)d_in[3];  // [32]
    const float* Wa    = (const float*)d_in[4];  // [128, 128]
    const float* va    = (const float*)d_in[5];  // [128]
    float*       out   = (float*)d_out;          // [128, 128]

    cudaFuncSetAttribute(dingo_kernel,
                         cudaFuncAttributeMaxDynamicSharedMemorySize, SMEM_BYTES);
    dingo_kernel<<<NB, TPB, SMEM_BYTES>>>(seq, emb, convw, convb, Wa, va, out);
}

// round 5
// speedup vs baseline: 2.9018x; 1.3890x over previous
#include <cuda_runtime.h>
#include <cuda_bf16.h>
#include <cstdint>

#define TPB     512
#define NB      128
#define SEQLEN  8194
#define NL      2048
#define DD      128
#define NT      128
#define NTILES  16
#define WSTR    272      // bytes per row (136 bf16) for W and H tiles

// shared memory layout (bytes)
#define OFF_WHI   0        // 128*272
#define OFF_WLO   34816
#define OFF_H     69632    // 2 parities x (hi 34816 + lo 34816) = 139264
#define OFF_MSH   208896   // 3*32*26 f32 = 9984
#define OFF_SSEQ  218880   // 4*132 i32 = 2112
#define OFF_VASH  220992   // 128 f32
#define OFF_EPART 221504   // 2 x 4 x 132 f32 = 4224
#define OFF_ESH   225728   // 128 f32
#define OFF_WSH   226240   // 128 f32
#define OFF_CTXB  226752   // 256 f32 = 1024
#define OFF_BSH   227776   // 32 f32
#define OFF_SCAL  227904   // 32 f32
#define SMEM_BYTES 228032

// named barriers: 1+p = HREADY, 3+p = GDONE, 5+p = EREADY, 7 = builder-internal
#define BAR_ARRIVE(id) asm volatile("bar.arrive %0, %1;" :: "r"(id), "r"(512) : "memory")
#define BAR_SYNC(id)   asm volatile("bar.sync %0, %1;"   :: "r"(id), "r"(512) : "memory")
#define BBAR()         asm volatile("bar.sync 7, 256;" ::: "memory")

__device__ __forceinline__ uint32_t smem_u32(const void* p) {
    uint32_t a;
    asm("{ .reg .u64 t; cvta.to.shared.u64 t, %1; cvt.u32.u64 %0, t; }" : "=r"(a) : "l"(p));
    return a;
}
__device__ __forceinline__ void ldsm_x4(uint32_t* r, uint32_t a) {
    asm volatile("ldmatrix.sync.aligned.m8n8.x4.shared.b16 {%0,%1,%2,%3}, [%4];"
                 : "=r"(r[0]), "=r"(r[1]), "=r"(r[2]), "=r"(r[3]) : "r"(a));
}
__device__ __forceinline__ void ldsm_x2(uint32_t& r0, uint32_t& r1, uint32_t a) {
    asm volatile("ldmatrix.sync.aligned.m8n8.x2.shared.b16 {%0,%1}, [%2];"
                 : "=r"(r0), "=r"(r1) : "r"(a));
}
__device__ __forceinline__ void mma16816(float* c, const uint32_t* a, uint32_t b0, uint32_t b1) {
    asm volatile("mma.sync.aligned.m16n8k16.row.col.f32.bf16.bf16.f32 "
                 "{%0,%1,%2,%3}, {%4,%5,%6,%7}, {%8,%9}, {%0,%1,%2,%3};"
                 : "+f"(c[0]), "+f"(c[1]), "+f"(c[2]), "+f"(c[3])
                 : "r"(a[0]), "r"(a[1]), "r"(a[2]), "r"(a[3]), "r"(b0), "r"(b1));
}
// accurate tanh: sign(x)*(1 - 2/(e^{2|x|}+1)); __expf rel err ~1e-7
__device__ __forceinline__ float tanh_acc(float x) {
    float ax = fminf(fabsf(x), 15.0f);
    float t  = __expf(2.0f * ax);
    float r  = 1.0f - __fdividef(2.0f, t + 1.0f);
    return copysignf(r, x);
}

// softmax scalars + online ctx update for tile with parity pp (builder threads)
__device__ __forceinline__ void builder_epilogue(
    int pp, int bt, int lane, char* smem, float* epart, float* esh, float* wsh,
    float* scal, float& ctxAcc)
{
    const float* ep = epart + pp * 528;
    if (bt < 128) {
        float e = ep[bt] + ep[132 + bt] + ep[264 + bt] + ep[396 + bt];
        esh[bt] = e;
        float mx = e;
        #pragma unroll
        for (int off = 16; off; off >>= 1)
            mx = fmaxf(mx, __shfl_xor_sync(0xffffffffu, mx, off));
        if (lane == 0) scal[8 + (bt >> 5)] = mx;
    }
    BBAR();
    if (bt == 0) {
        float mt = fmaxf(fmaxf(scal[8], scal[9]), fmaxf(scal[10], scal[11]));
        float m_new = fmaxf(scal[0], mt);
        scal[3] = __expf(scal[0] - m_new);   // alpha
        scal[2] = m_new;
        scal[0] = m_new;
    }
    BBAR();
    if (bt < 128) {
        float wv = __expf(esh[bt] - scal[2]);
        wsh[bt] = wv;
        #pragma unroll
        for (int off = 16; off; off >>= 1)
            wv += __shfl_xor_sync(0xffffffffu, wv, off);
        if (lane == 0) scal[16 + (bt >> 5)] = wv;
    }
    BBAR();
    if (bt == 0)
        scal[1] = scal[1] * scal[3] + (scal[16] + scal[17] + scal[18] + scal[19]);
    BBAR();
    const float alpha = scal[3];
    const int d = bt & 127, q = bt >> 7;
    const char* hb = smem + OFF_H + pp * 69632;
    float ta = 0.0f;
    #pragma unroll 4
    for (int i = 0; i < 64; i++) {
        int nn = q * 64 + i;
        uint32_t o = (uint32_t)nn * WSTR + (uint32_t)d * 2u;
        uint32_t hi16 = *(const unsigned short*)(hb + o);
        uint32_t lo16 = *(const unsigned short*)(hb + 34816 + o);
        ta += wsh[nn] * (__uint_as_float(hi16 << 16) + __uint_as_float(lo16 << 16));
    }
    ctxAcc = ctxAcc * alpha + ta;
}

__global__ void __launch_bounds__(TPB, 1)
dingo_kernel(const int*   __restrict__ seq,
             const float* __restrict__ emb,
             const float* __restrict__ convw,
             const float* __restrict__ convb,
             const float* __restrict__ Wa,
             const float* __restrict__ va,
             float*       __restrict__ out)
{
    extern __shared__ char smem[];
    const uint32_t sb = smem_u32(smem);
    float* Msh   = (float*)(smem + OFF_MSH);
    int*   sseq  = (int*)  (smem + OFF_SSEQ);
    float* vash  = (float*)(smem + OFF_VASH);
    float* epart = (float*)(smem + OFF_EPART);
    float* esh   = (float*)(smem + OFF_ESH);
    float* wsh   = (float*)(smem + OFF_WSH);
    float* ctxb  = (float*)(smem + OFF_CTXB);
    float* bsh   = (float*)(smem + OFF_BSH);
    float* scal  = (float*)(smem + OFF_SCAL);

    const int b    = blockIdx.x;
    const int tid  = threadIdx.x;
    const int wid  = tid >> 5;
    const int lane = tid & 31;
    const int* seqb = seq + b * SEQLEN;

    // ---- setup (all 512): W hi/lo split row-major [dw][e], conv fold ----
    for (int i = tid; i < DD * DD; i += TPB) {
        int dw = i >> 7, e = i & 127;
        float w = Wa[i];
        __nv_bfloat16 h = __float2bfloat16(w);
        float lo = w - __bfloat162float(h);
        __nv_bfloat16 l = __float2bfloat16(lo);
        *(__nv_bfloat16*)(smem + OFF_WHI + dw * WSTR + e * 2) = h;
        *(__nv_bfloat16*)(smem + OFF_WLO + dw * WSTR + e * 2) = l;
    }
    for (int i = tid; i < 3 * 32 * 26; i += TPB) {
        int k = i / 832, r = i - k * 832;
        int c = r / 26, tt = r - c * 26;
        float acc = 0.0f;
        #pragma unroll
        for (int q = 0; q < 5; q++)
            acc += emb[tt * 5 + q] * convw[(c * 5 + q) * 3 + k];
        Msh[(k * 32 + c) * 26 + tt] = acc;
    }
    if (tid < 32)  bsh[tid] = convb[tid];
    if (tid < 128) vash[tid] = va[tid];
    if (tid == 0) { scal[0] = -3.4e38f; scal[1] = 0.0f; }
    __syncthreads();

    if (tid < 256) {
        // ================= GEMM warps (0-7): m32 x n64 each =================
        const int gm = wid & 3, gn = wid >> 2;
        const uint32_t aBase = (uint32_t)(32 * gm + (lane & 15)) * WSTR
                             + (uint32_t)((lane >> 4) & 1) * 16u;
        const uint32_t aHi0 = sb + OFF_WHI + aBase;
        const uint32_t aHi1 = aHi0 + 16u * WSTR;
        const uint32_t aLo0 = sb + OFF_WLO + aBase;
        const uint32_t aLo1 = aLo0 + 16u * WSTR;
        const int ll = lane & 15;
        const uint32_t bBase = (uint32_t)(64 * gn + (ll & 7)) * WSTR
                             + (uint32_t)((ll >> 3) & 1) * 16u;
        const int g = lane >> 2, tc = lane & 3;
        const float v00 = vash[32 * gm + g],      v01 = vash[32 * gm + 8 + g];
        const float v10 = vash[32 * gm + 16 + g], v11 = vash[32 * gm + 24 + g];

        for (int tile = 0; tile < NTILES; tile++) {
            const int p = tile & 1;
            BAR_SYNC(1 + p);                       // H(tile) ready
            const uint32_t bHi = sb + OFF_H + (uint32_t)p * 69632u + bBase;
            const uint32_t bLo = bHi + 34816u;

            float acc[2][8][4];
            #pragma unroll
            for (int mi = 0; mi < 2; mi++)
                #pragma unroll
                for (int j = 0; j < 8; j++)
                    #pragma unroll
                    for (int q = 0; q < 4; q++) acc[mi][j][q] = 0.0f;

            #pragma unroll 1
            for (int kk = 0; kk < 8; kk++) {
                const uint32_t ko = (uint32_t)kk * 32u;
                uint32_t ah0[4], ah1[4], al0[4], al1[4];
                ldsm_x4(ah0, aHi0 + ko); ldsm_x4(ah1, aHi1 + ko);
                ldsm_x4(al0, aLo0 + ko); ldsm_x4(al1, aLo1 + ko);
                #pragma unroll
                for (int jh = 0; jh < 2; jh++) {
                    uint32_t bh[4][2], bl[4][2];
                    #pragma unroll
                    for (int j4 = 0; j4 < 4; j4++) {
                        const uint32_t bo = (uint32_t)(jh * 4 + j4) * (8u * WSTR) + ko;
                        ldsm_x2(bh[j4][0], bh[j4][1], bHi + bo);
                        ldsm_x2(bl[j4][0], bl[j4][1], bLo + bo);
                    }
                    #pragma unroll
                    for (int j4 = 0; j4 < 4; j4++) {
                        const int j = jh * 4 + j4;
                        mma16816(acc[0][j], ah0, bh[j4][0], bh[j4][1]);
                        mma16816(acc[1][j], ah1, bh[j4][0], bh[j4][1]);
                        mma16816(acc[0][j], ah0, bl[j4][0], bl[j4][1]);
                        mma16816(acc[1][j], ah1, bl[j4][0], bl[j4][1]);
                        mma16816(acc[0][j], al0, bh[j4][0], bh[j4][1]);
                        mma16816(acc[1][j], al1, bh[j4][0], bh[j4][1]);
                    }
                }
            }
            BAR_ARRIVE(3 + p);                     // done reading H(tile)

            // tanh + va weighting -> e partials for this warp's 32 dw rows
            float* ep = epart + p * 528 + gm * 132;
            #pragma unroll
            for (int j = 0; j < 8; j++) {
                float p0 = v00 * tanh_acc(acc[0][j][0]) + v01 * tanh_acc(acc[0][j][2])
                         + v10 * tanh_acc(acc[1][j][0]) + v11 * tanh_acc(acc[1][j][2]);
                float p1 = v00 * tanh_acc(acc[0][j][1]) + v01 * tanh_acc(acc[0][j][3])
                         + v10 * tanh_acc(acc[1][j][1]) + v11 * tanh_acc(acc[1][j][3]);
                #pragma unroll
                for (int off = 4; off <= 16; off <<= 1) {
                    p0 += __shfl_xor_sync(0xffffffffu, p0, off);
                    p1 += __shfl_xor_sync(0xffffffffu, p1, off);
                }
                if (lane < 4) {
                    ep[64 * gn + 8 * j + 2 * tc]     = p0;
                    ep[64 * gn + 8 * j + 2 * tc + 1] = p1;
                }
            }
            __threadfence_block();
            BAR_ARRIVE(5 + p);                     // e partials ready
        }
    } else {
        // ================= builder warps (8-15) =================
        const int bt = tid - 256;
        const int bn = bt & 127;
        const int ch = bt >> 7;
        float ctxAcc = 0.0f;

        for (int tile = 0; tile < NTILES; tile++) {
            const int p = tile & 1;
            BBAR();                                // prior tile reads done
            if (tile >= 2) BAR_SYNC(3 + p);        // GEMM(tile-2) done with buf p
            for (int i = bt; i < 4 * 130; i += 256) {
                int s = i / 130, o = i - s * 130;
                sseq[s * 132 + o] = seqb[s * NL + tile * NT + o];
            }
            BBAR();
            // build H(tile) into buf p: bf16 hi/lo, [n][e] rows
            {
                char* hb = smem + OFF_H + p * 69632;
                #pragma unroll
                for (int pr = 0; pr < 2; pr++) {
                    const int s0 = 2 * pr, s1 = s0 + 1;
                    const int a0 = sseq[s0*132+bn], a1 = sseq[s0*132+bn+1], a2 = sseq[s0*132+bn+2];
                    const int b0 = sseq[s1*132+bn], b1 = sseq[s1*132+bn+1], b2 = sseq[s1*132+bn+2];
                    const uint32_t rowb = (uint32_t)bn * WSTR + (uint32_t)(64 * ch + 2 * pr) * 2u;
                    #pragma unroll 4
                    for (int ci = 0; ci < 16; ci++) {
                        int c = ch * 16 + ci;
                        float bb = bsh[c];
                        float v0 = Msh[c*26+a0] + Msh[(32+c)*26+a1] + Msh[(64+c)*26+a2] + bb;
                        float v1 = Msh[c*26+b0] + Msh[(32+c)*26+b1] + Msh[(64+c)*26+b2] + bb;
                        v0 = fmaxf(v0, 0.0f); v1 = fmaxf(v1, 0.0f);
                        uint32_t hip;
                        asm("cvt.rn.bf16x2.f32 %0, %1, %2;" : "=r"(hip) : "f"(v1), "f"(v0));
                        float h0 = __uint_as_float(hip << 16);
                        float h1 = __uint_as_float(hip & 0xFFFF0000u);
                        float l0 = v0 - h0, l1 = v1 - h1;
                        uint32_t lop;
                        asm("cvt.rn.bf16x2.f32 %0, %1, %2;" : "=r"(lop) : "f"(l1), "f"(l0));
                        uint32_t off = rowb + (uint32_t)ci * 8u;
                        *(uint32_t*)(hb + off) = hip;
                        *(uint32_t*)(hb + 34816 + off) = lop;
                    }
                }
            }
            __threadfence_block();
            BAR_ARRIVE(1 + p);                     // H(tile) ready
            if (tile >= 1) {
                const int pp = (tile - 1) & 1;
                BAR_SYNC(5 + pp);                  // e partials(tile-1) ready
                builder_epilogue(pp, bt, lane, smem, epart, esh, wsh, scal, ctxAcc);
            }
        }
        // tail: epilogue for tile 15
        BAR_SYNC(5 + 1);
        builder_epilogue(1, bt, lane, smem, epart, esh, wsh, scal, ctxAcc);
        ctxb[bt] = ctxAcc;
    }

    __syncthreads();
    if (tid < 128) {
        float invz = 1.0f / scal[1];
        out[b * DD + tid] = (ctxb[tid] + ctxb[tid + 128]) * invz;
    }
}

extern "C" void kernel_launch(void* const* d_in, const int* in_sizes, int n_in,
                              void* d_out, int out_size)
{
    const int*   seq   = (const int*)  d_in[0];  // [128, 8194] int32
    const float* emb   = (const float*)d_in[1];  // [26, 5]
    const float* convw = (const float*)d_in[2];  // [32, 5, 3]
    const float* convb = (const float*)d_in[3];  // [32]
    const float* Wa    = (const float*)d_in[4];  // [128, 128]
    const float* va    = (const float*)d_in[5];  // [128]
    float*       out   = (float*)d_out;          // [128, 128]

    cudaFuncSetAttribute(dingo_kernel,
                         cudaFuncAttributeMaxDynamicSharedMemorySize, SMEM_BYTES);
    dingo_kernel<<<NB, TPB, SMEM_BYTES>>>(seq, emb, convw, convb, Wa, va, out);
}

// round 6
// speedup vs baseline: 3.9891x; 1.3747x over previous
#include <cuda_runtime.h>
#include <cuda_fp16.h>
#include <cstdint>

#define TPB     512
#define NB      128
#define SEQLEN  8194
#define NL      2048
#define DD      128
#define NT      128
#define NTILES  16
#define WSTR    272      // bytes per row (136 fp16) for W and H tiles

// shared memory layout (bytes)
#define OFF_WHI   0        // 128*272 = 34816
#define OFF_WLO   34816
#define OFF_H     69632    // 2 parities x 34816 (H fp16 single)
#define OFF_MSH   139264   // 3*32*33 f32 = 12672
#define OFF_SSEQ  151936   // 4*132 i32 = 2112
#define OFF_VASH  154048   // 128 f32
#define OFF_EPART 154560   // 2 x 4 x 132 f32 = 4224
#define OFF_ESH   158784   // 128 f32
#define OFF_WSH   159296   // 128 f32
#define OFF_CTXP  159808   // 8*128 f32 = 4096
#define OFF_SCAL  163904   // 32 f32
#define SMEM_BYTES 164032

// named barriers: 1+p = HREADY, 3+p = GDONE, 5+p = EREADY, 7 = builder-internal
#define BAR_ARRIVE(id) asm volatile("bar.arrive %0, %1;" :: "r"(id), "r"(512) : "memory")
#define BAR_SYNC(id)   asm volatile("bar.sync %0, %1;"   :: "r"(id), "r"(512) : "memory")
#define BBAR()         asm volatile("bar.sync 7, 256;" ::: "memory")

__device__ __forceinline__ uint32_t smem_u32(const void* p) {
    uint32_t a;
    asm("{ .reg .u64 t; cvta.to.shared.u64 t, %1; cvt.u32.u64 %0, t; }" : "=r"(a) : "l"(p));
    return a;
}
__device__ __forceinline__ void ldsm_x4(uint32_t* r, uint32_t a) {
    asm volatile("ldmatrix.sync.aligned.m8n8.x4.shared.b16 {%0,%1,%2,%3}, [%4];"
                 : "=r"(r[0]), "=r"(r[1]), "=r"(r[2]), "=r"(r[3]) : "r"(a));
}
__device__ __forceinline__ void ldsm_x2(uint32_t& r0, uint32_t& r1, uint32_t a) {
    asm volatile("ldmatrix.sync.aligned.m8n8.x2.shared.b16 {%0,%1}, [%2];"
                 : "=r"(r0), "=r"(r1) : "r"(a));
}
__device__ __forceinline__ void mma16816(float* c, const uint32_t* a, uint32_t b0, uint32_t b1) {
    asm volatile("mma.sync.aligned.m16n8k16.row.col.f32.f16.f16.f32 "
                 "{%0,%1,%2,%3}, {%4,%5,%6,%7}, {%8,%9}, {%0,%1,%2,%3};"
                 : "+f"(c[0]), "+f"(c[1]), "+f"(c[2]), "+f"(c[3])
                 : "r"(a[0]), "r"(a[1]), "r"(a[2]), "r"(a[3]), "r"(b0), "r"(b1));
}
// accurate tanh: sign(x)*(1 - 2/(e^{2|x|}+1)); __expf rel err ~1e-7
__device__ __forceinline__ float tanh_acc(float x) {
    float ax = fminf(fabsf(x), 15.0f);
    float t  = __expf(2.0f * ax);
    float r  = 1.0f - __fdividef(2.0f, t + 1.0f);
    return copysignf(r, x);
}

// softmax scalars for tile parity pp + online ctx update (builder threads)
__device__ __forceinline__ void builder_epilogue(
    int pp, int bt, int lane, int bw, char* smem, float* epart, float* esh,
    float* wsh, float* scal, float* ctxAcc)
{
    const float* ep = epart + pp * 528;
    if (bt < 128) {
        float e = ep[bt] + ep[132 + bt] + ep[264 + bt] + ep[396 + bt];
        esh[bt] = e;
        float mx = e;
        #pragma unroll
        for (int off = 16; off; off >>= 1)
            mx = fmaxf(mx, __shfl_xor_sync(0xffffffffu, mx, off));
        if (lane == 0) scal[8 + (bt >> 5)] = mx;
    }
    BBAR();
    if (bt == 0) {
        float mt = fmaxf(fmaxf(scal[8], scal[9]), fmaxf(scal[10], scal[11]));
        float m_new = fmaxf(scal[0], mt);
        scal[3] = __expf(scal[0] - m_new);   // alpha
        scal[2] = m_new;
        scal[0] = m_new;
    }
    BBAR();
    if (bt < 128) {
        float wv = __expf(esh[bt] - scal[2]);
        wsh[bt] = wv;
        #pragma unroll
        for (int off = 16; off; off >>= 1)
            wv += __shfl_xor_sync(0xffffffffu, wv, off);
        if (lane == 0) scal[16 + (bt >> 5)] = wv;
    }
    BBAR();
    if (bt == 0)
        scal[1] = scal[1] * scal[3] + (scal[16] + scal[17] + scal[18] + scal[19]);
    BBAR();
    // ctx: warp bw handles rows n = bw*16..+16; lane owns e-quad lane*4..+4
    const float alpha = scal[3];
    const char* hb = smem + OFF_H + pp * 34816;
    float t0 = 0.0f, t1 = 0.0f, t2 = 0.0f, t3 = 0.0f;
    #pragma unroll 4
    for (int i = 0; i < 16; i++) {
        int n = bw * 16 + i;
        float wv = wsh[n];
        uint2 hv = *(const uint2*)(hb + (uint32_t)n * WSTR + (uint32_t)lane * 8u);
        float2 f0 = __half22float2(*(__half2*)&hv.x);
        float2 f1 = __half22float2(*(__half2*)&hv.y);
        t0 += wv * f0.x; t1 += wv * f0.y; t2 += wv * f1.x; t3 += wv * f1.y;
    }
    ctxAcc[0] = ctxAcc[0] * alpha + t0;
    ctxAcc[1] = ctxAcc[1] * alpha + t1;
    ctxAcc[2] = ctxAcc[2] * alpha + t2;
    ctxAcc[3] = ctxAcc[3] * alpha + t3;
}

__global__ void __launch_bounds__(TPB, 1)
dingo_kernel(const int*   __restrict__ seq,
             const float* __restrict__ emb,
             const float* __restrict__ convw,
             const float* __restrict__ convb,
             const float* __restrict__ Wa,
             const float* __restrict__ va,
             float*       __restrict__ out)
{
    extern __shared__ char smem[];
    const uint32_t sb = smem_u32(smem);
    float* Msh   = (float*)(smem + OFF_MSH);   // [3][32][33], bias folded into k=0
    int*   sseq  = (int*)  (smem + OFF_SSEQ);
    float* vash  = (float*)(smem + OFF_VASH);
    float* epart = (float*)(smem + OFF_EPART);
    float* esh   = (float*)(smem + OFF_ESH);
    float* wsh   = (float*)(smem + OFF_WSH);
    float* ctxp  = (float*)(smem + OFF_CTXP);
    float* scal  = (float*)(smem + OFF_SCAL);

    const int b    = blockIdx.x;
    const int tid  = threadIdx.x;
    const int wid  = tid >> 5;
    const int lane = tid & 31;
    const int* seqb = seq + b * SEQLEN;

    // ---- setup (all 512): W fp16 hi/lo split row-major [dw][e]; tables ----
    for (int i = tid; i < DD * DD; i += TPB) {
        int dw = i >> 7, e = i & 127;
        float w = Wa[i];
        __half h = __float2half_rn(w);
        __half l = __float2half_rn(w - __half2float(h));
        *(__half*)(smem + OFF_WHI + dw * WSTR + e * 2) = h;
        *(__half*)(smem + OFF_WLO + dw * WSTR + e * 2) = l;
    }
    for (int i = tid; i < 3 * 32 * 26; i += TPB) {
        int k = i / 832, r = i - k * 832;
        int c = r / 26, tt = r - c * 26;
        float acc = (k == 0) ? convb[c] : 0.0f;
        #pragma unroll
        for (int q = 0; q < 5; q++)
            acc += emb[tt * 5 + q] * convw[(c * 5 + q) * 3 + k];
        Msh[(k * 32 + c) * 33 + tt] = acc;
    }
    if (tid < 128) vash[tid] = va[tid];
    if (tid == 0) { scal[0] = -3.4e38f; scal[1] = 0.0f; }
    __syncthreads();

    if (tid < 256) {
        // ================= GEMM warps (0-7): m32 x n64, fp16 2-term =========
        const int gm = wid & 3, gn = wid >> 2;
        const uint32_t aBase = (uint32_t)(32 * gm + (lane & 15)) * WSTR
                             + (uint32_t)((lane >> 4) & 1) * 16u;
        const uint32_t aHi0 = sb + OFF_WHI + aBase;
        const uint32_t aHi1 = aHi0 + 16u * WSTR;
        const uint32_t aLo0 = sb + OFF_WLO + aBase;
        const uint32_t aLo1 = aLo0 + 16u * WSTR;
        const int ll = lane & 15;
        const uint32_t bBase = (uint32_t)(64 * gn + (ll & 7)) * WSTR
                             + (uint32_t)((ll >> 3) & 1) * 16u;
        const int g = lane >> 2, tc = lane & 3;
        const float v00 = vash[32 * gm + g],      v01 = vash[32 * gm + 8 + g];
        const float v10 = vash[32 * gm + 16 + g], v11 = vash[32 * gm + 24 + g];

        for (int tile = 0; tile < NTILES; tile++) {
            const int p = tile & 1;
            BAR_SYNC(1 + p);                       // H(tile) ready
            const uint32_t bH = sb + OFF_H + (uint32_t)p * 34816u + bBase;

            float acc[2][8][4];
            #pragma unroll
            for (int mi = 0; mi < 2; mi++)
                #pragma unroll
                for (int j = 0; j < 8; j++)
                    #pragma unroll
                    for (int q = 0; q < 4; q++) acc[mi][j][q] = 0.0f;

            #pragma unroll 1
            for (int kk = 0; kk < 8; kk++) {
                const uint32_t ko = (uint32_t)kk * 32u;
                uint32_t ah0[4], ah1[4], al0[4], al1[4];
                ldsm_x4(ah0, aHi0 + ko); ldsm_x4(ah1, aHi1 + ko);
                ldsm_x4(al0, aLo0 + ko); ldsm_x4(al1, aLo1 + ko);
                #pragma unroll
                for (int jh = 0; jh < 2; jh++) {
                    uint32_t bh[4][2];
                    #pragma unroll
                    for (int j4 = 0; j4 < 4; j4++) {
                        const uint32_t bo = (uint32_t)(jh * 4 + j4) * (8u * WSTR) + ko;
                        ldsm_x2(bh[j4][0], bh[j4][1], bH + bo);
                    }
                    #pragma unroll
                    for (int j4 = 0; j4 < 4; j4++) {
                        const int j = jh * 4 + j4;
                        mma16816(acc[0][j], ah0, bh[j4][0], bh[j4][1]);
                        mma16816(acc[1][j], ah1, bh[j4][0], bh[j4][1]);
                        mma16816(acc[0][j], al0, bh[j4][0], bh[j4][1]);
                        mma16816(acc[1][j], al1, bh[j4][0], bh[j4][1]);
                    }
                }
            }
            BAR_ARRIVE(3 + p);                     // done reading H(tile)

            // tanh + va weighting -> e partials for this warp's 32 dw rows
            float* ep = epart + p * 528 + gm * 132;
            #pragma unroll
            for (int j = 0; j < 8; j++) {
                float p0 = v00 * tanh_acc(acc[0][j][0]) + v01 * tanh_acc(acc[0][j][2])
                         + v10 * tanh_acc(acc[1][j][0]) + v11 * tanh_acc(acc[1][j][2]);
                float p1 = v00 * tanh_acc(acc[0][j][1]) + v01 * tanh_acc(acc[0][j][3])
                         + v10 * tanh_acc(acc[1][j][1]) + v11 * tanh_acc(acc[1][j][3]);
                #pragma unroll
                for (int off = 4; off <= 16; off <<= 1) {
                    p0 += __shfl_xor_sync(0xffffffffu, p0, off);
                    p1 += __shfl_xor_sync(0xffffffffu, p1, off);
                }
                if (lane < 4) {
                    ep[64 * gn + 8 * j + 2 * tc]     = p0;
                    ep[64 * gn + 8 * j + 2 * tc + 1] = p1;
                }
            }
            __threadfence_block();
            BAR_ARRIVE(5 + p);                     // e partials ready
        }
    } else {
        // ================= builder warps (8-15) =================
        const int bt = tid - 256;
        const int bw = bt >> 5;            // builder warp 0-7
        const int c  = lane;               // channel
        const float* M0 = Msh + c * 33;           // bias folded in
        const float* M1 = Msh + (32 + c) * 33;
        const float* M2 = Msh + (64 + c) * 33;
        float ctxAcc[4] = {0.0f, 0.0f, 0.0f, 0.0f};

        for (int tile = 0; tile < NTILES; tile++) {
            const int p = tile & 1;
            BBAR();                                // prior tile reads done
            if (tile >= 2) BAR_SYNC(3 + p);        // GEMM(tile-2) done with buf p
            for (int i = bt; i < 4 * 130; i += 256) {
                int s = i / 130, o = i - s * 130;
                sseq[s * 132 + o] = seqb[s * NL + tile * NT + o];
            }
            BBAR();
            // build H(tile) into buf p: fp16, [n][e] rows; warp bw owns 16 n
            {
                char* hb = smem + OFF_H + p * 34816;
                const int nb = bw * 16;
                int u0[4], u1[4];
                #pragma unroll
                for (int s = 0; s < 4; s++) {
                    u0[s] = sseq[s * 132 + nb];
                    u1[s] = sseq[s * 132 + nb + 1];
                }
                #pragma unroll 2
                for (int i = 0; i < 16; i++) {
                    const int n = nb + i;
                    float v[4];
                    #pragma unroll
                    for (int s = 0; s < 4; s++) {
                        int u2 = sseq[s * 132 + n + 2];
                        v[s] = fmaxf(M0[u0[s]] + M1[u1[s]] + M2[u2], 0.0f);
                        u0[s] = u1[s]; u1[s] = u2;
                    }
                    uint32_t pk0, pk1;
                    asm("cvt.rn.f16x2.f32 %0, %1, %2;" : "=r"(pk0) : "f"(v[1]), "f"(v[0]));
                    asm("cvt.rn.f16x2.f32 %0, %1, %2;" : "=r"(pk1) : "f"(v[3]), "f"(v[2]));
                    uint2 pk = make_uint2(pk0, pk1);
                    *(uint2*)(hb + (uint32_t)n * WSTR + (uint32_t)c * 8u) = pk;
                }
            }
            __threadfence_block();
            BAR_ARRIVE(1 + p);                     // H(tile) ready
            if (tile >= 1) {
                const int pp = (tile - 1) & 1;
                BAR_SYNC(5 + pp);                  // e partials(tile-1) ready
                builder_epilogue(pp, bt, lane, bw, smem, epart, esh, wsh, scal, ctxAcc);
            }
        }
        // tail: epilogue for tile 15 (parity 1)
        BAR_SYNC(5 + 1);
        builder_epilogue(1, bt, lane, bw, smem, epart, esh, wsh, scal, ctxAcc);
        #pragma unroll
        for (int j = 0; j < 4; j++)
            ctxp[bw * 128 + lane * 4 + j] = ctxAcc[j];
    }

    __syncthreads();
    if (tid < 128) {
        float invz = 1.0f / scal[1];
        float s = 0.0f;
        #pragma unroll
        for (int q = 0; q < 8; q++) s += ctxp[q * 128 + tid];
        out[b * DD + tid] = s * invz;
    }
}

extern "C" void kernel_launch(void* const* d_in, const int* in_sizes, int n_in,
                              void* d_out, int out_size)
{
    const int*   seq   = (const int*)  d_in[0];  // [128, 8194] int32
    const float* emb   = (const float*)d_in[1];  // [26, 5]
    const float* convw = (const float*)d_in[2];  // [32, 5, 3]
    const float* convb = (const float*)d_in[3];  // [32]
    const float* Wa    = (const float*)d_in[4];  // [128, 128]
    const float* va    = (const float*)d_in[5];  // [128]
    float*       out   = (float*)d_out;          // [128, 128]

    cudaFuncSetAttribute(dingo_kernel,
                         cudaFuncAttributeMaxDynamicSharedMemorySize, SMEM_BYTES);
    dingo_kernel<<<NB, TPB, SMEM_BYTES>>>(seq, emb, convw, convb, Wa, va, out);
}